// round 3
// baseline (speedup 1.0000x reference)
#include <cuda_runtime.h>

#define N_NODES 50000
#define N_EDGES 640000
// IN_DIM = OUT_DIM = 128, H = 4, D = 32

// ---------------- scratch (device globals; no allocation allowed) ------------
__device__ __align__(16) float g_Wh[N_NODES * 128];
__device__ __align__(16) float g_sl[N_NODES * 4];
__device__ __align__(16) float g_sr[N_NODES * 4];
__device__ __align__(16) float g_sattn[N_EDGES * 4];   // attn logits in dst-sorted order
__device__ int g_ssrc[N_EDGES];                        // src node in dst-sorted order
__device__ int g_cnt[N_NODES];
__device__ int g_offs[N_NODES + 1];
__device__ int g_cursor[N_NODES];

// ---------------- f32x2 packed FMA helpers (ptxas never emits FFMA2 itself) --
union U64F2 { unsigned long long u; float2 f; };

__device__ __forceinline__ unsigned long long fma2(unsigned long long a,
                                                   unsigned long long b,
                                                   unsigned long long c) {
    unsigned long long d;
    asm("fma.rn.f32x2 %0, %1, %2, %3;" : "=l"(d) : "l"(a), "l"(b), "l"(c));
    return d;
}

// ---------------- CSR build --------------------------------------------------
__global__ void k_zero() {
    int i = blockIdx.x * blockDim.x + threadIdx.x;
    if (i < N_NODES) g_cnt[i] = 0;
}

__global__ void __launch_bounds__(256) k_count(const int* __restrict__ ei) {
    int e = blockIdx.x * blockDim.x + threadIdx.x;
    if (e < N_EDGES) atomicAdd(&g_cnt[ei[N_EDGES + e]], 1);
}

// single-block scan of 50K counters -> offsets + cursor
__global__ void __launch_bounds__(1024) k_scan() {
    __shared__ int sp[1024];
    const int CH = (N_NODES + 1023) / 1024;   // 49
    int t  = threadIdx.x;
    int lo = t * CH;
    int hi = lo + CH < N_NODES ? lo + CH : N_NODES;

    int s = 0;
    for (int i = lo; i < hi; i++) s += g_cnt[i];
    sp[t] = s;
    __syncthreads();
    for (int off = 1; off < 1024; off <<= 1) {
        int v = (t >= off) ? sp[t - off] : 0;
        __syncthreads();
        sp[t] += v;
        __syncthreads();
    }
    int run = (t > 0) ? sp[t - 1] : 0;
    for (int i = lo; i < hi; i++) {
        g_offs[i]   = run;
        g_cursor[i] = run;
        run += g_cnt[i];
    }
    if (t == 1023) g_offs[N_NODES] = sp[1023];
}

// ---------------- K1: Wh = h @ W^T (f32x2), plus s_l / s_r epilogue ----------
// block = 256 (8 warps), warp handles 4 rows. Lane owns column pairs
// (2*lane, 2*lane+1) and (64+2*lane, 64+2*lane+1).
__global__ void __launch_bounds__(256) k_gemm(const float* __restrict__ h,
                                              const float* __restrict__ W,
                                              const float* __restrict__ a) {
    __shared__ float Ws[64 * 134];   // stride 134 (even) -> 8B-aligned float2 rows
    const int tid  = threadIdx.x;
    const int lane = tid & 31;
    const int warp = tid >> 5;
    const int rowbase = blockIdx.x * 32 + warp * 4;

    unsigned long long acc2[4][2];
#pragma unroll
    for (int r = 0; r < 4; r++) { acc2[r][0] = 0ull; acc2[r][1] = 0ull; }

    // attention vector entries for this lane's 4 columns
    const int hA = lane >> 4;          // head of cols 2l, 2l+1   (0 or 1)
    const int hB = hA + 2;             // head of cols 64+2l, 65+2l
    const int d0 = (2 * lane) & 31;
    const int d1 = d0 + 1;
    const float al0 = a[hA * 64 + d0],      al1 = a[hA * 64 + d1];
    const float al2 = a[hB * 64 + d0],      al3 = a[hB * 64 + d1];
    const float ar0 = a[hA * 64 + 32 + d0], ar1 = a[hA * 64 + 32 + d1];
    const float ar2 = a[hB * 64 + 32 + d0], ar3 = a[hB * 64 + 32 + d1];

    const float4* h4 = reinterpret_cast<const float4*>(h);

    for (int p = 0; p < 2; p++) {
        __syncthreads();
        for (int i = tid; i < 128 * 64; i += 256) {
            int c = i >> 6;
            int k = i & 63;
            Ws[k * 134 + c] = W[c * 128 + p * 64 + k];   // Ws[k][c] = W^T
        }
        __syncthreads();

#pragma unroll 1
        for (int k4 = 0; k4 < 16; k4++) {
            float4 hv[4];
#pragma unroll
            for (int r = 0; r < 4; r++) {
                int row = rowbase + r;
                int rr  = row < N_NODES ? row : N_NODES - 1;
                hv[r] = h4[rr * 32 + p * 16 + k4];
            }
#pragma unroll
            for (int kk = 0; kk < 4; kk++) {
                int k = k4 * 4 + kk;
                U64F2 w0, w1;
                w0.f = *reinterpret_cast<const float2*>(&Ws[k * 134 + 2 * lane]);
                w1.f = *reinterpret_cast<const float2*>(&Ws[k * 134 + 64 + 2 * lane]);
#pragma unroll
                for (int r = 0; r < 4; r++) {
                    float hk = (kk == 0) ? hv[r].x : (kk == 1) ? hv[r].y
                             : (kk == 2) ? hv[r].z : hv[r].w;
                    U64F2 hk2; hk2.f = make_float2(hk, hk);
                    acc2[r][0] = fma2(hk2.u, w0.u, acc2[r][0]);
                    acc2[r][1] = fma2(hk2.u, w1.u, acc2[r][1]);
                }
            }
        }
    }

    // epilogue
#pragma unroll
    for (int r = 0; r < 4; r++) {
        int row = rowbase + r;
        if (row >= N_NODES) break;
        U64F2 t0, t1; t0.u = acc2[r][0]; t1.u = acc2[r][1];
        const float a0 = t0.f.x, a1 = t0.f.y, a2 = t1.f.x, a3 = t1.f.y;

        *reinterpret_cast<float2*>(&g_Wh[row * 128 + 2 * lane])      = t0.f;
        *reinterpret_cast<float2*>(&g_Wh[row * 128 + 64 + 2 * lane]) = t1.f;

        float p01l = a0 * al0 + a1 * al1, p23l = a2 * al2 + a3 * al3;
        float p01r = a0 * ar0 + a1 * ar1, p23r = a2 * ar2 + a3 * ar3;
        bool lo16 = (lane < 16);
        float phl[4] = { lo16 ? p01l : 0.f, lo16 ? 0.f : p01l,
                         lo16 ? p23l : 0.f, lo16 ? 0.f : p23l };
        float phr[4] = { lo16 ? p01r : 0.f, lo16 ? 0.f : p01r,
                         lo16 ? p23r : 0.f, lo16 ? 0.f : p23r };
#pragma unroll
        for (int j = 0; j < 4; j++) {
#pragma unroll
            for (int o = 16; o > 0; o >>= 1) {
                phl[j] += __shfl_xor_sync(0xffffffffu, phl[j], o);
                phr[j] += __shfl_xor_sync(0xffffffffu, phr[j], o);
            }
            if (lane == 0) {
                g_sl[row * 4 + j] = phl[j];
                g_sr[row * 4 + j] = phr[j];
            }
        }
    }
}

// ---------------- K2: attention logits, written in dst-sorted order ----------
__global__ void __launch_bounds__(256) k_attn_fill(const int* __restrict__ ei,
                                                   const float* __restrict__ ef,
                                                   const float* __restrict__ We) {
    __shared__ float sWe[64];
    if (threadIdx.x < 64) sWe[threadIdx.x] = We[threadIdx.x];
    __syncthreads();

    int e = blockIdx.x * blockDim.x + threadIdx.x;
    if (e >= N_EDGES) return;

    int s = ei[e];
    int d = ei[N_EDGES + e];

    float4 l4 = *reinterpret_cast<const float4*>(&g_sl[s * 4]);
    float4 r4 = *reinterpret_cast<const float4*>(&g_sr[d * 4]);
    float lv[4] = {l4.x, l4.y, l4.z, l4.w};
    float rv[4] = {r4.x, r4.y, r4.z, r4.w};

    float efv[16];
    const float4* ef4 = reinterpret_cast<const float4*>(ef + (size_t)e * 16);
#pragma unroll
    for (int q = 0; q < 4; q++) {
        float4 t = ef4[q];
        efv[q * 4 + 0] = t.x; efv[q * 4 + 1] = t.y;
        efv[q * 4 + 2] = t.z; efv[q * 4 + 3] = t.w;
    }

    float att[4];
#pragma unroll
    for (int hh = 0; hh < 4; hh++) {
        float x = lv[hh] + rv[hh];
        x = x > 0.0f ? x : 0.2f * x;           // leaky_relu(0.2)
        float dot = 0.0f;
#pragma unroll
        for (int q = 0; q < 16; q++) dot += efv[q] * sWe[hh * 16 + q];
        att[hh] = x + dot;
    }

    int pos = atomicAdd(&g_cursor[d], 1);
    reinterpret_cast<float4*>(g_sattn)[pos] =
        make_float4(att[0], att[1], att[2], att[3]);
    g_ssrc[pos] = s;
}

// ---------------- K3: gather aggregate + softmax + GELU + LayerNorm ----------
// one warp per destination node; no atomics anywhere.
__global__ void __launch_bounds__(256) k_agg_final(const float* __restrict__ ln_s,
                                                   const float* __restrict__ ln_b,
                                                   float* __restrict__ out) {
    int gw   = (blockIdx.x * blockDim.x + threadIdx.x) >> 5;
    int lane = threadIdx.x & 31;
    if (gw >= N_NODES) return;

    int beg = g_offs[gw];
    int end = g_offs[gw + 1];

    const float4* attn4 = reinterpret_cast<const float4*>(g_sattn);
    const float4* wh4   = reinterpret_cast<const float4*>(g_Wh);

    // pass A: per-head max over incoming edges
    float4 mx = make_float4(-1e9f, -1e9f, -1e9f, -1e9f);
    for (int i = beg + lane; i < end; i += 32) {
        float4 t = attn4[i];
        mx.x = fmaxf(mx.x, t.x); mx.y = fmaxf(mx.y, t.y);
        mx.z = fmaxf(mx.z, t.z); mx.w = fmaxf(mx.w, t.w);
    }
#pragma unroll
    for (int o = 16; o > 0; o >>= 1) {
        mx.x = fmaxf(mx.x, __shfl_xor_sync(0xffffffffu, mx.x, o));
        mx.y = fmaxf(mx.y, __shfl_xor_sync(0xffffffffu, mx.y, o));
        mx.z = fmaxf(mx.z, __shfl_xor_sync(0xffffffffu, mx.z, o));
        mx.w = fmaxf(mx.w, __shfl_xor_sync(0xffffffffu, mx.w, o));
    }

    // pass B: per-head denom
    float4 dn = make_float4(0.f, 0.f, 0.f, 0.f);
    for (int i = beg + lane; i < end; i += 32) {
        float4 t = attn4[i];
        dn.x += __expf(t.x - mx.x); dn.y += __expf(t.y - mx.y);
        dn.z += __expf(t.z - mx.z); dn.w += __expf(t.w - mx.w);
    }
#pragma unroll
    for (int o = 16; o > 0; o >>= 1) {
        dn.x += __shfl_xor_sync(0xffffffffu, dn.x, o);
        dn.y += __shfl_xor_sync(0xffffffffu, dn.y, o);
        dn.z += __shfl_xor_sync(0xffffffffu, dn.z, o);
        dn.w += __shfl_xor_sync(0xffffffffu, dn.w, o);
    }

    // pass C: weighted gather (lane owns cols 4*lane..4*lane+3; head = lane/8)
    int head  = lane >> 3;
    float mxh = head == 0 ? mx.x : head == 1 ? mx.y : head == 2 ? mx.z : mx.w;
    float dnh = head == 0 ? dn.x : head == 1 ? dn.y : head == 2 ? dn.z : dn.w;

    float acc0 = 0.f, acc1 = 0.f, acc2 = 0.f, acc3 = 0.f;
    for (int i = beg; i < end; i++) {
        int s = g_ssrc[i];                 // warp-uniform -> broadcast
        float4 t = attn4[i];               // warp-uniform 16B -> broadcast
        float ah = head == 0 ? t.x : head == 1 ? t.y : head == 2 ? t.z : t.w;
        float sc = __expf(ah - mxh);
        float4 v = wh4[s * 32 + lane];
        acc0 += v.x * sc; acc1 += v.y * sc; acc2 += v.z * sc; acc3 += v.w * sc;
    }

    float inv = 1.0f / (dnh + 1e-9f);
    float x0 = acc0 * inv, x1 = acc1 * inv, x2 = acc2 * inv, x3 = acc3 * inv;

    // exact GELU
    const float kc = 0.70710678118654752f;
    x0 = 0.5f * x0 * (1.0f + erff(x0 * kc));
    x1 = 0.5f * x1 * (1.0f + erff(x1 * kc));
    x2 = 0.5f * x2 * (1.0f + erff(x2 * kc));
    x3 = 0.5f * x3 * (1.0f + erff(x3 * kc));

    // LayerNorm over 128
    float ssum = x0 + x1 + x2 + x3;
#pragma unroll
    for (int o = 16; o > 0; o >>= 1) ssum += __shfl_xor_sync(0xffffffffu, ssum, o);
    float mu = ssum * (1.0f / 128.0f);

    float c0 = x0 - mu, c1 = x1 - mu, c2 = x2 - mu, c3 = x3 - mu;
    float vsum = c0 * c0 + c1 * c1 + c2 * c2 + c3 * c3;
#pragma unroll
    for (int o = 16; o > 0; o >>= 1) vsum += __shfl_xor_sync(0xffffffffu, vsum, o);
    float rstd = rsqrtf(vsum * (1.0f / 128.0f) + 1e-5f);

    float4 g = reinterpret_cast<const float4*>(ln_s)[lane];
    float4 b = reinterpret_cast<const float4*>(ln_b)[lane];
    float4 o4;
    o4.x = c0 * rstd * g.x + b.x;
    o4.y = c1 * rstd * g.y + b.y;
    o4.z = c2 * rstd * g.z + b.z;
    o4.w = c3 * rstd * g.w + b.w;
    reinterpret_cast<float4*>(out + (size_t)gw * 128)[lane] = o4;
}

// ---------------- launch -----------------------------------------------------
extern "C" void kernel_launch(void* const* d_in, const int* in_sizes, int n_in,
                              void* d_out, int out_size) {
    const float* h    = (const float*)d_in[0];
    const int*   ei   = (const int*)d_in[1];
    const float* ef   = (const float*)d_in[2];
    const float* W    = (const float*)d_in[3];
    const float* We   = (const float*)d_in[4];
    const float* a    = (const float*)d_in[5];
    const float* ln_s = (const float*)d_in[6];
    const float* ln_b = (const float*)d_in[7];
    float* out = (float*)d_out;

    k_zero<<<(N_NODES + 255) / 256, 256>>>();
    k_count<<<(N_EDGES + 255) / 256, 256>>>(ei);
    k_scan<<<1, 1024>>>();
    k_gemm<<<(N_NODES + 31) / 32, 256>>>(h, W, a);
    k_attn_fill<<<(N_EDGES + 255) / 256, 256>>>(ei, ef, We);
    k_agg_final<<<(N_NODES * 32 + 255) / 256, 256>>>(ln_s, ln_b, out);
}

// round 4
// speedup vs baseline: 1.2195x; 1.2195x over previous
#include <cuda_runtime.h>

#define N_NODES 50000
#define N_EDGES 640000
#define NB_CNT ((N_NODES + 255) / 256)   // 196 count blocks
// IN_DIM = OUT_DIM = 128, H = 4, D = 32

// ---------------- scratch (device globals; no allocation allowed) ------------
__device__ __align__(16) float g_Wh[N_NODES * 128];
__device__ __align__(16) float g_sl[N_NODES * 4];
__device__ __align__(16) float g_sr[N_NODES * 4];
__device__ __align__(16) float g_sattn[N_EDGES * 4];   // attn logits, dst-sorted
__device__ int g_ssrc[N_EDGES];                        // src node, dst-sorted
__device__ int g_cnt[N_NODES];
__device__ int g_offs[N_NODES + 1];
__device__ int g_cursor[N_NODES];
__device__ int g_part[NB_CNT + 1];

// ---------------- f32x2 packed FMA ------------------------------------------
union U64F2 { unsigned long long u; float2 f; };

__device__ __forceinline__ unsigned long long fma2(unsigned long long a,
                                                   unsigned long long b,
                                                   unsigned long long c) {
    unsigned long long d;
    asm("fma.rn.f32x2 %0, %1, %2, %3;" : "=l"(d) : "l"(a), "l"(b), "l"(c));
    return d;
}

// ---------------- CSR build (parallel) ---------------------------------------
__global__ void k_zero() {
    int i = blockIdx.x * blockDim.x + threadIdx.x;
    if (i < N_NODES) g_cnt[i] = 0;
}

__global__ void __launch_bounds__(256) k_count(const int* __restrict__ ei) {
    int e = blockIdx.x * blockDim.x + threadIdx.x;
    if (e < N_EDGES) atomicAdd(&g_cnt[ei[N_EDGES + e]], 1);
}

// per-block sums of counts
__global__ void __launch_bounds__(256) k_bsum() {
    __shared__ int sw[8];
    int t = threadIdx.x;
    int i = blockIdx.x * 256 + t;
    int c = (i < N_NODES) ? g_cnt[i] : 0;
#pragma unroll
    for (int o = 16; o > 0; o >>= 1) c += __shfl_xor_sync(0xffffffffu, c, o);
    if ((t & 31) == 0) sw[t >> 5] = c;
    __syncthreads();
    if (t == 0) {
        int s = 0;
#pragma unroll
        for (int w = 0; w < 8; w++) s += sw[w];
        g_part[blockIdx.x] = s;
    }
}

// scan the 196 partials (single small block)
__global__ void __launch_bounds__(256) k_scan_part() {
    __shared__ int sd[256];
    int t = threadIdx.x;
    int v = (t < NB_CNT) ? g_part[t] : 0;
    sd[t] = v;
    __syncthreads();
    for (int o = 1; o < 256; o <<= 1) {
        int u = (t >= o) ? sd[t - o] : 0;
        __syncthreads();
        sd[t] += u;
        __syncthreads();
    }
    if (t < NB_CNT) g_part[t] = sd[t] - v;    // exclusive prefix
    if (t == 255) g_offs[N_NODES] = sd[255];  // total (= N_EDGES)
}

// final offsets = block prefix + intra-block exclusive scan
__global__ void __launch_bounds__(256) k_offs() {
    __shared__ int sd[256];
    int t = threadIdx.x;
    int i = blockIdx.x * 256 + t;
    int c = (i < N_NODES) ? g_cnt[i] : 0;
    sd[t] = c;
    __syncthreads();
    for (int o = 1; o < 256; o <<= 1) {
        int u = (t >= o) ? sd[t - o] : 0;
        __syncthreads();
        sd[t] += u;
        __syncthreads();
    }
    if (i < N_NODES) {
        int off = g_part[blockIdx.x] + sd[t] - c;
        g_offs[i]   = off;
        g_cursor[i] = off;
    }
}

// ---------------- K1: Wh = h @ W^T (f32x2, 8 rows/warp) ----------------------
// block = 256 (8 warps); warp handles 8 rows; lane owns column pairs
// (2*lane, 2*lane+1) and (64+2*lane, 64+2*lane+1).
__global__ void __launch_bounds__(256) k_gemm(const float* __restrict__ h,
                                              const float* __restrict__ W,
                                              const float* __restrict__ a) {
    __shared__ float Ws[64 * 134];   // stride 134 (even) -> 8B-aligned float2
    const int tid  = threadIdx.x;
    const int lane = tid & 31;
    const int warp = tid >> 5;
    const int rowbase = blockIdx.x * 64 + warp * 8;

    unsigned long long acc2[8][2];
#pragma unroll
    for (int r = 0; r < 8; r++) { acc2[r][0] = 0ull; acc2[r][1] = 0ull; }

    int rowidx[8];
#pragma unroll
    for (int r = 0; r < 8; r++) {
        int row = rowbase + r;
        rowidx[r] = (row < N_NODES ? row : N_NODES - 1) * 32;
    }

    const float4* h4 = reinterpret_cast<const float4*>(h);

    for (int p = 0; p < 2; p++) {
        __syncthreads();
        for (int i = tid; i < 128 * 64; i += 256) {
            int c = i >> 6;
            int k = i & 63;
            Ws[k * 134 + c] = W[c * 128 + p * 64 + k];   // Ws[k][c] = W^T
        }
        __syncthreads();

#pragma unroll 1
        for (int k4 = 0; k4 < 16; k4++) {
            float4 hv[8];
#pragma unroll
            for (int r = 0; r < 8; r++) hv[r] = h4[rowidx[r] + p * 16 + k4];
#pragma unroll
            for (int kk = 0; kk < 4; kk++) {
                int k = k4 * 4 + kk;
                U64F2 w0, w1;
                w0.f = *reinterpret_cast<const float2*>(&Ws[k * 134 + 2 * lane]);
                w1.f = *reinterpret_cast<const float2*>(&Ws[k * 134 + 64 + 2 * lane]);
#pragma unroll
                for (int r = 0; r < 8; r++) {
                    float hk = (kk == 0) ? hv[r].x : (kk == 1) ? hv[r].y
                             : (kk == 2) ? hv[r].z : hv[r].w;
                    U64F2 hk2; hk2.f = make_float2(hk, hk);
                    acc2[r][0] = fma2(hk2.u, w0.u, acc2[r][0]);
                    acc2[r][1] = fma2(hk2.u, w1.u, acc2[r][1]);
                }
            }
        }
    }

    // epilogue: attention coefficients for this lane's 4 columns
    const int hA = lane >> 4;          // head of cols 2l, 2l+1
    const int hB = hA + 2;             // head of cols 64+2l, 65+2l
    const int d0 = (2 * lane) & 31;
    const int d1 = d0 + 1;
    const float al0 = a[hA * 64 + d0],      al1 = a[hA * 64 + d1];
    const float al2 = a[hB * 64 + d0],      al3 = a[hB * 64 + d1];
    const float ar0 = a[hA * 64 + 32 + d0], ar1 = a[hA * 64 + 32 + d1];
    const float ar2 = a[hB * 64 + 32 + d0], ar3 = a[hB * 64 + 32 + d1];

#pragma unroll
    for (int r = 0; r < 8; r++) {
        int row = rowbase + r;
        if (row >= N_NODES) break;
        U64F2 t0, t1; t0.u = acc2[r][0]; t1.u = acc2[r][1];
        const float a0 = t0.f.x, a1 = t0.f.y, a2 = t1.f.x, a3 = t1.f.y;

        *reinterpret_cast<float2*>(&g_Wh[row * 128 + 2 * lane])      = t0.f;
        *reinterpret_cast<float2*>(&g_Wh[row * 128 + 64 + 2 * lane]) = t1.f;

        float p01l = a0 * al0 + a1 * al1, p23l = a2 * al2 + a3 * al3;
        float p01r = a0 * ar0 + a1 * ar1, p23r = a2 * ar2 + a3 * ar3;
        // reduce within each 16-lane half (heads split by lane<16 / lane>=16)
#pragma unroll
        for (int o = 1; o < 16; o <<= 1) {
            p01l += __shfl_xor_sync(0xffffffffu, p01l, o);
            p23l += __shfl_xor_sync(0xffffffffu, p23l, o);
            p01r += __shfl_xor_sync(0xffffffffu, p01r, o);
            p23r += __shfl_xor_sync(0xffffffffu, p23r, o);
        }
        if (lane == 0) {
            g_sl[row * 4 + 0] = p01l; g_sl[row * 4 + 2] = p23l;
            g_sr[row * 4 + 0] = p01r; g_sr[row * 4 + 2] = p23r;
        } else if (lane == 16) {
            g_sl[row * 4 + 1] = p01l; g_sl[row * 4 + 3] = p23l;
            g_sr[row * 4 + 1] = p01r; g_sr[row * 4 + 3] = p23r;
        }
    }
}

// ---------------- K2: attention logits, written in dst-sorted order ----------
__global__ void __launch_bounds__(256) k_attn_fill(const int* __restrict__ ei,
                                                   const float* __restrict__ ef,
                                                   const float* __restrict__ We) {
    __shared__ float sWe[64];
    if (threadIdx.x < 64) sWe[threadIdx.x] = We[threadIdx.x];
    __syncthreads();

    int e = blockIdx.x * blockDim.x + threadIdx.x;
    if (e >= N_EDGES) return;

    int s = ei[e];
    int d = ei[N_EDGES + e];

    float4 l4 = *reinterpret_cast<const float4*>(&g_sl[s * 4]);
    float4 r4 = *reinterpret_cast<const float4*>(&g_sr[d * 4]);
    float lv[4] = {l4.x, l4.y, l4.z, l4.w};
    float rv[4] = {r4.x, r4.y, r4.z, r4.w};

    float efv[16];
    const float4* ef4 = reinterpret_cast<const float4*>(ef + (size_t)e * 16);
#pragma unroll
    for (int q = 0; q < 4; q++) {
        float4 t = ef4[q];
        efv[q * 4 + 0] = t.x; efv[q * 4 + 1] = t.y;
        efv[q * 4 + 2] = t.z; efv[q * 4 + 3] = t.w;
    }

    float att[4];
#pragma unroll
    for (int hh = 0; hh < 4; hh++) {
        float x = lv[hh] + rv[hh];
        x = x > 0.0f ? x : 0.2f * x;           // leaky_relu(0.2)
        float dot = 0.0f;
#pragma unroll
        for (int q = 0; q < 16; q++) dot += efv[q] * sWe[hh * 16 + q];
        att[hh] = x + dot;
    }

    int pos = atomicAdd(&g_cursor[d], 1);
    reinterpret_cast<float4*>(g_sattn)[pos] =
        make_float4(att[0], att[1], att[2], att[3]);
    g_ssrc[pos] = s;
}

// ---------------- K3: gather aggregate + softmax + GELU + LayerNorm ----------
__device__ __forceinline__ float hsel(float4 t, int head) {
    return head == 0 ? t.x : head == 1 ? t.y : head == 2 ? t.z : t.w;
}

__global__ void __launch_bounds__(256) k_agg_final(const float* __restrict__ ln_s,
                                                   const float* __restrict__ ln_b,
                                                   float* __restrict__ out) {
    int gw   = (blockIdx.x * blockDim.x + threadIdx.x) >> 5;
    int lane = threadIdx.x & 31;
    if (gw >= N_NODES) return;

    int beg = g_offs[gw];
    int end = g_offs[gw + 1];

    const float4* attn4 = reinterpret_cast<const float4*>(g_sattn);
    const float4* wh4   = reinterpret_cast<const float4*>(g_Wh);

    // pass A: per-head max (lanes stride edges)
    float4 mx = make_float4(-1e9f, -1e9f, -1e9f, -1e9f);
    for (int i = beg + lane; i < end; i += 32) {
        float4 t = attn4[i];
        mx.x = fmaxf(mx.x, t.x); mx.y = fmaxf(mx.y, t.y);
        mx.z = fmaxf(mx.z, t.z); mx.w = fmaxf(mx.w, t.w);
    }
#pragma unroll
    for (int o = 16; o > 0; o >>= 1) {
        mx.x = fmaxf(mx.x, __shfl_xor_sync(0xffffffffu, mx.x, o));
        mx.y = fmaxf(mx.y, __shfl_xor_sync(0xffffffffu, mx.y, o));
        mx.z = fmaxf(mx.z, __shfl_xor_sync(0xffffffffu, mx.z, o));
        mx.w = fmaxf(mx.w, __shfl_xor_sync(0xffffffffu, mx.w, o));
    }

    // pass B: per-head denom
    float4 dn = make_float4(0.f, 0.f, 0.f, 0.f);
    for (int i = beg + lane; i < end; i += 32) {
        float4 t = attn4[i];
        dn.x += __expf(t.x - mx.x); dn.y += __expf(t.y - mx.y);
        dn.z += __expf(t.z - mx.z); dn.w += __expf(t.w - mx.w);
    }
#pragma unroll
    for (int o = 16; o > 0; o >>= 1) {
        dn.x += __shfl_xor_sync(0xffffffffu, dn.x, o);
        dn.y += __shfl_xor_sync(0xffffffffu, dn.y, o);
        dn.z += __shfl_xor_sync(0xffffffffu, dn.z, o);
        dn.w += __shfl_xor_sync(0xffffffffu, dn.w, o);
    }

    // pass C: weighted gather (lane owns cols 4*lane..4*lane+3; head = lane/8)
    const int head  = lane >> 3;
    const float mxh = hsel(mx, head);
    const float dnh = hsel(dn, head);

    float acc0 = 0.f, acc1 = 0.f, acc2 = 0.f, acc3 = 0.f;
    int i = beg;
    for (; i + 3 < end; i += 4) {             // MLP=4: 4 independent gathers
        int s0 = g_ssrc[i], s1 = g_ssrc[i + 1], s2 = g_ssrc[i + 2], s3 = g_ssrc[i + 3];
        float4 t0 = attn4[i],     t1 = attn4[i + 1];
        float4 t2 = attn4[i + 2], t3 = attn4[i + 3];
        float4 v0 = wh4[s0 * 32 + lane];
        float4 v1 = wh4[s1 * 32 + lane];
        float4 v2 = wh4[s2 * 32 + lane];
        float4 v3 = wh4[s3 * 32 + lane];
        float sc0 = __expf(hsel(t0, head) - mxh);
        float sc1 = __expf(hsel(t1, head) - mxh);
        float sc2 = __expf(hsel(t2, head) - mxh);
        float sc3 = __expf(hsel(t3, head) - mxh);
        acc0 += v0.x * sc0 + v1.x * sc1 + v2.x * sc2 + v3.x * sc3;
        acc1 += v0.y * sc0 + v1.y * sc1 + v2.y * sc2 + v3.y * sc3;
        acc2 += v0.z * sc0 + v1.z * sc1 + v2.z * sc2 + v3.z * sc3;
        acc3 += v0.w * sc0 + v1.w * sc1 + v2.w * sc2 + v3.w * sc3;
    }
    for (; i < end; i++) {
        int s = g_ssrc[i];
        float4 t = attn4[i];
        float sc = __expf(hsel(t, head) - mxh);
        float4 v = wh4[s * 32 + lane];
        acc0 += v.x * sc; acc1 += v.y * sc; acc2 += v.z * sc; acc3 += v.w * sc;
    }

    float inv = 1.0f / (dnh + 1e-9f);
    float x0 = acc0 * inv, x1 = acc1 * inv, x2 = acc2 * inv, x3 = acc3 * inv;

    // exact GELU
    const float kc = 0.70710678118654752f;
    x0 = 0.5f * x0 * (1.0f + erff(x0 * kc));
    x1 = 0.5f * x1 * (1.0f + erff(x1 * kc));
    x2 = 0.5f * x2 * (1.0f + erff(x2 * kc));
    x3 = 0.5f * x3 * (1.0f + erff(x3 * kc));

    // LayerNorm over 128
    float ssum = x0 + x1 + x2 + x3;
#pragma unroll
    for (int o = 16; o > 0; o >>= 1) ssum += __shfl_xor_sync(0xffffffffu, ssum, o);
    float mu = ssum * (1.0f / 128.0f);

    float c0 = x0 - mu, c1 = x1 - mu, c2 = x2 - mu, c3 = x3 - mu;
    float vsum = c0 * c0 + c1 * c1 + c2 * c2 + c3 * c3;
#pragma unroll
    for (int o = 16; o > 0; o >>= 1) vsum += __shfl_xor_sync(0xffffffffu, vsum, o);
    float rstd = rsqrtf(vsum * (1.0f / 128.0f) + 1e-5f);

    float4 g = reinterpret_cast<const float4*>(ln_s)[lane];
    float4 b = reinterpret_cast<const float4*>(ln_b)[lane];
    float4 o4;
    o4.x = c0 * rstd * g.x + b.x;
    o4.y = c1 * rstd * g.y + b.y;
    o4.z = c2 * rstd * g.z + b.z;
    o4.w = c3 * rstd * g.w + b.w;
    reinterpret_cast<float4*>(out + (size_t)gw * 128)[lane] = o4;
}

// ---------------- launch -----------------------------------------------------
extern "C" void kernel_launch(void* const* d_in, const int* in_sizes, int n_in,
                              void* d_out, int out_size) {
    const float* h    = (const float*)d_in[0];
    const int*   ei   = (const int*)d_in[1];
    const float* ef   = (const float*)d_in[2];
    const float* W    = (const float*)d_in[3];
    const float* We   = (const float*)d_in[4];
    const float* a    = (const float*)d_in[5];
    const float* ln_s = (const float*)d_in[6];
    const float* ln_b = (const float*)d_in[7];
    float* out = (float*)d_out;

    k_zero<<<NB_CNT, 256>>>();
    k_count<<<(N_EDGES + 255) / 256, 256>>>(ei);
    k_bsum<<<NB_CNT, 256>>>();
    k_scan_part<<<1, 256>>>();
    k_offs<<<NB_CNT, 256>>>();
    k_gemm<<<(N_NODES + 63) / 64, 256>>>(h, W, a);
    k_attn_fill<<<(N_EDGES + 255) / 256, 256>>>(ei, ef, We);
    k_agg_final<<<(N_NODES * 32 + 255) / 256, 256>>>(ln_s, ln_b, out);
}

// round 7
// speedup vs baseline: 2.1388x; 1.7538x over previous
#include <cuda_runtime.h>
#include <cuda_fp16.h>

#define N_NODES 50000
#define N_EDGES 640000
#define NB_CNT ((N_NODES + 255) / 256)   // 196 count blocks
// IN_DIM = OUT_DIM = 128, H = 4, D = 32

// ---------------- scratch (device globals; no allocation allowed) ------------
__device__ __align__(16) __half g_Wh[N_NODES * 128];   // fp16 Wh
__device__ __align__(16) float g_sl[N_NODES * 4];
__device__ __align__(16) float g_sr[N_NODES * 4];
__device__ __align__(16) float g_sattn[N_EDGES * 4];   // attn logits, dst-sorted
__device__ int g_ssrc[N_EDGES];                        // src node, dst-sorted
__device__ int g_cnt[N_NODES];
__device__ int g_offs[N_NODES + 1];
__device__ int g_cursor[N_NODES];
__device__ int g_part[NB_CNT + 1];

// ---------------- CSR build (parallel) ---------------------------------------
__global__ void k_zero() {
    int i = blockIdx.x * blockDim.x + threadIdx.x;
    if (i < N_NODES) g_cnt[i] = 0;
}

__global__ void __launch_bounds__(256) k_count(const int* __restrict__ ei) {
    int e = blockIdx.x * blockDim.x + threadIdx.x;
    if (e < N_EDGES) atomicAdd(&g_cnt[ei[N_EDGES + e]], 1);
}

__global__ void __launch_bounds__(256) k_bsum() {
    __shared__ int sw[8];
    int t = threadIdx.x;
    int i = blockIdx.x * 256 + t;
    int c = (i < N_NODES) ? g_cnt[i] : 0;
#pragma unroll
    for (int o = 16; o > 0; o >>= 1) c += __shfl_xor_sync(0xffffffffu, c, o);
    if ((t & 31) == 0) sw[t >> 5] = c;
    __syncthreads();
    if (t == 0) {
        int s = 0;
#pragma unroll
        for (int w = 0; w < 8; w++) s += sw[w];
        g_part[blockIdx.x] = s;
    }
}

__global__ void __launch_bounds__(256) k_scan_part() {
    __shared__ int sd[256];
    int t = threadIdx.x;
    int v = (t < NB_CNT) ? g_part[t] : 0;
    sd[t] = v;
    __syncthreads();
    for (int o = 1; o < 256; o <<= 1) {
        int u = (t >= o) ? sd[t - o] : 0;
        __syncthreads();
        sd[t] += u;
        __syncthreads();
    }
    if (t < NB_CNT) g_part[t] = sd[t] - v;    // exclusive prefix
    if (t == 255) g_offs[N_NODES] = sd[255];
}

__global__ void __launch_bounds__(256) k_offs() {
    __shared__ int sd[256];
    int t = threadIdx.x;
    int i = blockIdx.x * 256 + t;
    int c = (i < N_NODES) ? g_cnt[i] : 0;
    sd[t] = c;
    __syncthreads();
    for (int o = 1; o < 256; o <<= 1) {
        int u = (t >= o) ? sd[t - o] : 0;
        __syncthreads();
        sd[t] += u;
        __syncthreads();
    }
    if (i < N_NODES) {
        int off = g_part[blockIdx.x] + sd[t] - c;
        g_offs[i]   = off;
        g_cursor[i] = off;
    }
}

// ---------------- K1: Wh = h @ W^T via fp16 tensor-core MMA ------------------
// Block tile 128x128, 8 warps = 4(m) x 2(n). Warp: 32 rows x 64 cols
// = 2 m16-tiles x 8 n8-tiles, K staged in two 64-wide fp16 smem phases.
__device__ __forceinline__ unsigned smem_u32(const void* p) {
    return (unsigned)__cvta_generic_to_shared(p);
}

__global__ void __launch_bounds__(256) k_gemm(const float* __restrict__ h,
                                              const float* __restrict__ W) {
    __shared__ __half As[128 * 72];   // padded rows: 72 halfs = 144B (16B mult)
    __shared__ __half Bs[128 * 72];   // Bs[n][k] = W[n][k]
    const int tid  = threadIdx.x;
    const int lane = tid & 31;
    const int warp = tid >> 5;
    const int m0 = (warp >> 1) * 32;      // warp row base within block
    const int n0 = (warp & 1) * 64;       // warp col base within block
    const int rowbase = blockIdx.x * 128;

    float acc[2][8][4];
#pragma unroll
    for (int mt = 0; mt < 2; mt++)
#pragma unroll
        for (int nt = 0; nt < 8; nt++)
#pragma unroll
            for (int q = 0; q < 4; q++) acc[mt][nt][q] = 0.0f;

    const float4* h4 = reinterpret_cast<const float4*>(h);
    const float4* W4 = reinterpret_cast<const float4*>(W);

    for (int phase = 0; phase < 2; phase++) {
        __syncthreads();
        {
            int r  = tid >> 4;       // 0..15
            int c4 = tid & 15;       // float4 index within 64 cols
#pragma unroll
            for (int it = 0; it < 8; it++) {
                int row  = r + it * 16;
                int grow = rowbase + row;
                if (grow >= N_NODES) grow = N_NODES - 1;
                float4 v = h4[grow * 32 + phase * 16 + c4];
                __half2* dst = reinterpret_cast<__half2*>(&As[row * 72 + c4 * 4]);
                dst[0] = __floats2half2_rn(v.x, v.y);
                dst[1] = __floats2half2_rn(v.z, v.w);
            }
#pragma unroll
            for (int it = 0; it < 8; it++) {
                int n = r + it * 16;
                float4 v = W4[n * 32 + phase * 16 + c4];
                __half2* dst = reinterpret_cast<__half2*>(&Bs[n * 72 + c4 * 4]);
                dst[0] = __floats2half2_rn(v.x, v.y);
                dst[1] = __floats2half2_rn(v.z, v.w);
            }
        }
        __syncthreads();

#pragma unroll
        for (int ks = 0; ks < 4; ks++) {
            const int k = ks * 16;
            // A fragments: 2 m16-tiles
            unsigned a[2][4];
#pragma unroll
            for (int mt = 0; mt < 2; mt++) {
                int row = m0 + mt * 16 + (lane & 15);
                int col = k + (lane >> 4) * 8;
                unsigned addr = smem_u32(&As[row * 72 + col]);
                asm volatile(
                    "ldmatrix.sync.aligned.m8n8.x4.shared.b16 {%0,%1,%2,%3}, [%4];"
                    : "=r"(a[mt][0]), "=r"(a[mt][1]), "=r"(a[mt][2]), "=r"(a[mt][3])
                    : "r"(addr));
            }
            // B fragments: 8 n8-tiles, two per ldmatrix.x4
            unsigned b[8][2];
#pragma unroll
            for (int nt2 = 0; nt2 < 4; nt2++) {
                int n   = n0 + nt2 * 16 + (lane >> 4) * 8 + (lane & 7);
                int col = k + ((lane >> 3) & 1) * 8;
                unsigned addr = smem_u32(&Bs[n * 72 + col]);
                unsigned r0, r1, r2, r3;
                asm volatile(
                    "ldmatrix.sync.aligned.m8n8.x4.shared.b16 {%0,%1,%2,%3}, [%4];"
                    : "=r"(r0), "=r"(r1), "=r"(r2), "=r"(r3)
                    : "r"(addr));
                b[nt2 * 2][0]     = r0; b[nt2 * 2][1]     = r1;
                b[nt2 * 2 + 1][0] = r2; b[nt2 * 2 + 1][1] = r3;
            }
#pragma unroll
            for (int mt = 0; mt < 2; mt++)
#pragma unroll
                for (int nt = 0; nt < 8; nt++) {
                    asm volatile(
                        "mma.sync.aligned.m16n8k16.row.col.f32.f16.f16.f32 "
                        "{%0,%1,%2,%3}, {%4,%5,%6,%7}, {%8,%9}, {%0,%1,%2,%3};"
                        : "+f"(acc[mt][nt][0]), "+f"(acc[mt][nt][1]),
                          "+f"(acc[mt][nt][2]), "+f"(acc[mt][nt][3])
                        : "r"(a[mt][0]), "r"(a[mt][1]), "r"(a[mt][2]), "r"(a[mt][3]),
                          "r"(b[nt][0]), "r"(b[nt][1]));
                }
        }
    }

    // epilogue: d frag -> half2 stores. d0,d1: row l/4, cols 2(l%4)+{0,1};
    // d2,d3: row l/4+8, same cols.
#pragma unroll
    for (int mt = 0; mt < 2; mt++) {
        int r0 = rowbase + m0 + mt * 16 + (lane >> 2);
        int r1 = r0 + 8;
#pragma unroll
        for (int nt = 0; nt < 8; nt++) {
            int col = n0 + nt * 8 + (lane & 3) * 2;
            if (r0 < N_NODES)
                *reinterpret_cast<__half2*>(&g_Wh[r0 * 128 + col]) =
                    __floats2half2_rn(acc[mt][nt][0], acc[mt][nt][1]);
            if (r1 < N_NODES)
                *reinterpret_cast<__half2*>(&g_Wh[r1 * 128 + col]) =
                    __floats2half2_rn(acc[mt][nt][2], acc[mt][nt][3]);
        }
    }
}

// ---------------- K1b: s_l / s_r from fp16 Wh (warp per node) ----------------
__global__ void __launch_bounds__(256) k_sides(const float* __restrict__ a) {
    int gw   = (blockIdx.x * blockDim.x + threadIdx.x) >> 5;
    int lane = threadIdx.x & 31;
    if (gw >= N_NODES) return;

    int head = lane >> 3;            // cols lane*4..lane*4+3 all in head lane/8
    int d    = (lane & 7) * 4;       // dim-within-head base

    uint2 pv = reinterpret_cast<const uint2*>(g_Wh)[gw * 32 + lane];
    float2 f0 = __half22float2(*reinterpret_cast<__half2*>(&pv.x));
    float2 f1 = __half22float2(*reinterpret_cast<__half2*>(&pv.y));

    const float* ah = a + head * 64;
    float sl = f0.x * ah[d]      + f0.y * ah[d + 1]
             + f1.x * ah[d + 2]  + f1.y * ah[d + 3];
    float sr = f0.x * ah[32 + d]     + f0.y * ah[32 + d + 1]
             + f1.x * ah[32 + d + 2] + f1.y * ah[32 + d + 3];
#pragma unroll
    for (int o = 1; o < 8; o <<= 1) {
        sl += __shfl_xor_sync(0xffffffffu, sl, o);
        sr += __shfl_xor_sync(0xffffffffu, sr, o);
    }
    if ((lane & 7) == 0) {
        g_sl[gw * 4 + head] = sl;
        g_sr[gw * 4 + head] = sr;
    }
}

// ---------------- K2: attention logits, written in dst-sorted order ----------
__global__ void __launch_bounds__(256) k_attn_fill(const int* __restrict__ ei,
                                                   const float* __restrict__ ef,
                                                   const float* __restrict__ We) {
    __shared__ float sWe[64];
    if (threadIdx.x < 64) sWe[threadIdx.x] = We[threadIdx.x];
    __syncthreads();

    int e = blockIdx.x * blockDim.x + threadIdx.x;
    if (e >= N_EDGES) return;

    int s = ei[e];
    int d = ei[N_EDGES + e];

    float4 l4 = *reinterpret_cast<const float4*>(&g_sl[s * 4]);
    float4 r4 = *reinterpret_cast<const float4*>(&g_sr[d * 4]);
    float lv[4] = {l4.x, l4.y, l4.z, l4.w};
    float rv[4] = {r4.x, r4.y, r4.z, r4.w};

    float efv[16];
    const float4* ef4 = reinterpret_cast<const float4*>(ef + (size_t)e * 16);
#pragma unroll
    for (int q = 0; q < 4; q++) {
        float4 t = ef4[q];
        efv[q * 4 + 0] = t.x; efv[q * 4 + 1] = t.y;
        efv[q * 4 + 2] = t.z; efv[q * 4 + 3] = t.w;
    }

    float att[4];
#pragma unroll
    for (int hh = 0; hh < 4; hh++) {
        float x = lv[hh] + rv[hh];
        x = x > 0.0f ? x : 0.2f * x;           // leaky_relu(0.2)
        float dot = 0.0f;
#pragma unroll
        for (int q = 0; q < 16; q++) dot += efv[q] * sWe[hh * 16 + q];
        att[hh] = x + dot;
    }

    int pos = atomicAdd(&g_cursor[d], 1);
    reinterpret_cast<float4*>(g_sattn)[pos] =
        make_float4(att[0], att[1], att[2], att[3]);
    g_ssrc[pos] = s;
}

// ---------------- K3: gather aggregate + softmax + GELU + LayerNorm ----------
__device__ __forceinline__ float hsel(float4 t, int head) {
    return head == 0 ? t.x : head == 1 ? t.y : head == 2 ? t.z : t.w;
}

__global__ void __launch_bounds__(256) k_agg_final(const float* __restrict__ ln_s,
                                                   const float* __restrict__ ln_b,
                                                   float* __restrict__ out) {
    int gw   = (blockIdx.x * blockDim.x + threadIdx.x) >> 5;
    int lane = threadIdx.x & 31;
    if (gw >= N_NODES) return;

    int beg = g_offs[gw];
    int end = g_offs[gw + 1];

    const float4* attn4 = reinterpret_cast<const float4*>(g_sattn);
    const uint2*  wh2   = reinterpret_cast<const uint2*>(g_Wh);

    // pass A: per-head max
    float4 mx = make_float4(-1e9f, -1e9f, -1e9f, -1e9f);
    for (int i = beg + lane; i < end; i += 32) {
        float4 t = attn4[i];
        mx.x = fmaxf(mx.x, t.x); mx.y = fmaxf(mx.y, t.y);
        mx.z = fmaxf(mx.z, t.z); mx.w = fmaxf(mx.w, t.w);
    }
#pragma unroll
    for (int o = 16; o > 0; o >>= 1) {
        mx.x = fmaxf(mx.x, __shfl_xor_sync(0xffffffffu, mx.x, o));
        mx.y = fmaxf(mx.y, __shfl_xor_sync(0xffffffffu, mx.y, o));
        mx.z = fmaxf(mx.z, __shfl_xor_sync(0xffffffffu, mx.z, o));
        mx.w = fmaxf(mx.w, __shfl_xor_sync(0xffffffffu, mx.w, o));
    }

    // pass B: per-head denom
    float4 dn = make_float4(0.f, 0.f, 0.f, 0.f);
    for (int i = beg + lane; i < end; i += 32) {
        float4 t = attn4[i];
        dn.x += __expf(t.x - mx.x); dn.y += __expf(t.y - mx.y);
        dn.z += __expf(t.z - mx.z); dn.w += __expf(t.w - mx.w);
    }
#pragma unroll
    for (int o = 16; o > 0; o >>= 1) {
        dn.x += __shfl_xor_sync(0xffffffffu, dn.x, o);
        dn.y += __shfl_xor_sync(0xffffffffu, dn.y, o);
        dn.z += __shfl_xor_sync(0xffffffffu, dn.z, o);
        dn.w += __shfl_xor_sync(0xffffffffu, dn.w, o);
    }

    // pass C: weighted gather (lane owns cols 4*lane..4*lane+3; head = lane/8)
    const int head  = lane >> 3;
    const float mxh = hsel(mx, head);
    const float dnh = hsel(dn, head);

    float acc0 = 0.f, acc1 = 0.f, acc2 = 0.f, acc3 = 0.f;
    int i = beg;
    for (; i + 3 < end; i += 4) {             // MLP=4 gathers in flight
        int s0 = g_ssrc[i], s1 = g_ssrc[i + 1], s2 = g_ssrc[i + 2], s3 = g_ssrc[i + 3];
        float4 t0 = attn4[i],     t1 = attn4[i + 1];
        float4 t2 = attn4[i + 2], t3 = attn4[i + 3];
        uint2 p0 = wh2[s0 * 32 + lane];
        uint2 p1 = wh2[s1 * 32 + lane];
        uint2 p2 = wh2[s2 * 32 + lane];
        uint2 p3 = wh2[s3 * 32 + lane];
        float sc0 = __expf(hsel(t0, head) - mxh);
        float sc1 = __expf(hsel(t1, head) - mxh);
        float sc2 = __expf(hsel(t2, head) - mxh);
        float sc3 = __expf(hsel(t3, head) - mxh);
        float2 a0 = __half22float2(*reinterpret_cast<__half2*>(&p0.x));
        float2 b0 = __half22float2(*reinterpret_cast<__half2*>(&p0.y));
        float2 a1 = __half22float2(*reinterpret_cast<__half2*>(&p1.x));
        float2 b1 = __half22float2(*reinterpret_cast<__half2*>(&p1.y));
        float2 a2 = __half22float2(*reinterpret_cast<__half2*>(&p2.x));
        float2 b2 = __half22float2(*reinterpret_cast<__half2*>(&p2.y));
        float2 a3 = __half22float2(*reinterpret_cast<__half2*>(&p3.x));
        float2 b3 = __half22float2(*reinterpret_cast<__half2*>(&p3.y));
        acc0 += a0.x * sc0 + a1.x * sc1 + a2.x * sc2 + a3.x * sc3;
        acc1 += a0.y * sc0 + a1.y * sc1 + a2.y * sc2 + a3.y * sc3;
        acc2 += b0.x * sc0 + b1.x * sc1 + b2.x * sc2 + b3.x * sc3;
        acc3 += b0.y * sc0 + b1.y * sc1 + b2.y * sc2 + b3.y * sc3;
    }
    for (; i < end; i++) {
        int s = g_ssrc[i];
        float4 t = attn4[i];
        float sc = __expf(hsel(t, head) - mxh);
        uint2 p = wh2[s * 32 + lane];
        float2 fa = __half22float2(*reinterpret_cast<__half2*>(&p.x));
        float2 fb = __half22float2(*reinterpret_cast<__half2*>(&p.y));
        acc0 += fa.x * sc; acc1 += fa.y * sc; acc2 += fb.x * sc; acc3 += fb.y * sc;
    }

    float inv = 1.0f / (dnh + 1e-9f);
    float x0 = acc0 * inv, x1 = acc1 * inv, x2 = acc2 * inv, x3 = acc3 * inv;

    // exact GELU
    const float kc = 0.70710678118654752f;
    x0 = 0.5f * x0 * (1.0f + erff(x0 * kc));
    x1 = 0.5f * x1 * (1.0f + erff(x1 * kc));
    x2 = 0.5f * x2 * (1.0f + erff(x2 * kc));
    x3 = 0.5f * x3 * (1.0f + erff(x3 * kc));

    // LayerNorm over 128
    float ssum = x0 + x1 + x2 + x3;
#pragma unroll
    for (int o = 16; o > 0; o >>= 1) ssum += __shfl_xor_sync(0xffffffffu, ssum, o);
    float mu = ssum * (1.0f / 128.0f);

    float c0 = x0 - mu, c1 = x1 - mu, c2 = x2 - mu, c3 = x3 - mu;
    float vsum = c0 * c0 + c1 * c1 + c2 * c2 + c3 * c3;
#pragma unroll
    for (int o = 16; o > 0; o >>= 1) vsum += __shfl_xor_sync(0xffffffffu, vsum, o);
    float rstd = rsqrtf(vsum * (1.0f / 128.0f) + 1e-5f);

    float4 g = reinterpret_cast<const float4*>(ln_s)[lane];
    float4 b = reinterpret_cast<const float4*>(ln_b)[lane];
    float4 o4;
    o4.x = c0 * rstd * g.x + b.x;
    o4.y = c1 * rstd * g.y + b.y;
    o4.z = c2 * rstd * g.z + b.z;
    o4.w = c3 * rstd * g.w + b.w;
    reinterpret_cast<float4*>(out + (size_t)gw * 128)[lane] = o4;
}

// ---------------- launch -----------------------------------------------------
extern "C" void kernel_launch(void* const* d_in, const int* in_sizes, int n_in,
                              void* d_out, int out_size) {
    const float* h    = (const float*)d_in[0];
    const int*   ei   = (const int*)d_in[1];
    const float* ef   = (const float*)d_in[2];
    const float* W    = (const float*)d_in[3];
    const float* We   = (const float*)d_in[4];
    const float* a    = (const float*)d_in[5];
    const float* ln_s = (const float*)d_in[6];
    const float* ln_b = (const float*)d_in[7];
    float* out = (float*)d_out;

    k_zero<<<NB_CNT, 256>>>();
    k_count<<<(N_EDGES + 255) / 256, 256>>>(ei);
    k_bsum<<<NB_CNT, 256>>>();
    k_scan_part<<<1, 256>>>();
    k_offs<<<NB_CNT, 256>>>();
    k_gemm<<<(N_NODES + 127) / 128, 256>>>(h, W);
    k_sides<<<(N_NODES * 32 + 255) / 256, 256>>>(a);
    k_attn_fill<<<(N_EDGES + 255) / 256, 256>>>(ei, ef, We);
    k_agg_final<<<(N_NODES * 32 + 255) / 256, 256>>>(ln_s, ln_b, out);
}